// round 3
// baseline (speedup 1.0000x reference)
#include <cuda_runtime.h>
#include <math.h>

#define Bx 512
#define Tx 256
#define Ix 256
#define Hx 512
#define G4 2048   // 4*Hx

// Scratch (allocation-free rule: __device__ globals)
__device__ float g_xg[(size_t)Tx * Bx * G4];   // [t][b][4H]  (1 GB)
__device__ float g_hs[(size_t)Tx * Bx * Hx];   // [t][b][H]   (256 MB)
__device__ float g_h0[Bx * Hx];
__device__ float g_c [Bx * Hx];
// Whh reorganized: [jt=32][k=512][j=16][g=4]  (gate-interleaved, tile-contiguous)
__device__ float g_wr[(size_t)Hx * G4];

// ---- packed f32x2 helpers ---------------------------------------------------
__device__ __forceinline__ unsigned long long pack2(float a, float b) {
    unsigned long long r;
    asm("mov.b64 %0, {%1, %2};" : "=l"(r) : "f"(a), "f"(b));
    return r;
}
__device__ __forceinline__ void unpack2(unsigned long long v, float& a, float& b) {
    asm("mov.b64 {%0, %1}, %2;" : "=f"(a), "=f"(b) : "l"(v));
}
__device__ __forceinline__ void ffma2(unsigned long long& d,
                                      unsigned long long a,
                                      unsigned long long b) {
    asm("fma.rn.f32x2 %0, %1, %2, %0;" : "+l"(d) : "l"(a), "l"(b));
}

// ---------------------------------------------------------------------------
__global__ void init_kernel() {
    int i = blockIdx.x * blockDim.x + threadIdx.x;
    if (i < Bx * Hx) { g_h0[i] = 0.f; g_c[i] = 0.f; }
}

// One-time Whh reorg: g_wr[((jt*512 + k)*16 + j)*4 + g] = Whh[(g*Hx + jt*16 + j)*Hx + k]
__global__ __launch_bounds__(256) void reorg_kernel(const float* __restrict__ Whh) {
    int i = blockIdx.x * blockDim.x + threadIdx.x;   // 0 .. Hx*G4-1
    if (i >= Hx * G4) return;
    int g  = i & 3;
    int j  = (i >> 2) & 15;
    int k  = (i >> 6) & 511;
    int jt = i >> 15;
    g_wr[i] = Whh[((size_t)g * Hx + jt * 16 + j) * Hx + k];
}

// ---------------------------------------------------------------------------
// xg[t][b][j] = sum_i x[b][t][i] * Wih[j][i] + bih[j] + bhh[j]
__global__ __launch_bounds__(256) void pregemm_kernel(
    const float* __restrict__ x, const float* __restrict__ Wih,
    const float* __restrict__ bih, const float* __restrict__ bhh)
{
    __shared__ float sx[16][68];
    __shared__ float sw[16][68];
    const int tid = threadIdx.x;
    const int tx = tid & 15, ty = tid >> 4;
    const int j0 = blockIdx.x * 64, b0 = blockIdx.y * 64, t = blockIdx.z;

    unsigned long long acc[4][2];
    #pragma unroll
    for (int i = 0; i < 4; i++) { acc[i][0] = 0ULL; acc[i][1] = 0ULL; }

    const int r = tid >> 2;
    const int q = (tid & 3) * 4;
    const float* xrow = x + ((size_t)(b0 + r) * Tx + t) * Ix;
    const float* wrow = Wih + (size_t)(j0 + r) * Ix;

    for (int k0 = 0; k0 < Ix; k0 += 16) {
        float4 xv = *(const float4*)(xrow + k0 + q);
        float4 wv = *(const float4*)(wrow + k0 + q);
        sx[q + 0][r] = xv.x; sx[q + 1][r] = xv.y; sx[q + 2][r] = xv.z; sx[q + 3][r] = xv.w;
        sw[q + 0][r] = wv.x; sw[q + 1][r] = wv.y; sw[q + 2][r] = wv.z; sw[q + 3][r] = wv.w;
        __syncthreads();
        #pragma unroll
        for (int k = 0; k < 16; k++) {
            float4 xf = *(float4*)&sx[k][ty * 4];
            unsigned long long wA = *(const unsigned long long*)&sw[k][tx * 4];
            unsigned long long wB = *(const unsigned long long*)&sw[k][tx * 4 + 2];
            unsigned long long hh[4];
            hh[0] = pack2(xf.x, xf.x); hh[1] = pack2(xf.y, xf.y);
            hh[2] = pack2(xf.z, xf.z); hh[3] = pack2(xf.w, xf.w);
            #pragma unroll
            for (int i = 0; i < 4; i++) {
                ffma2(acc[i][0], hh[i], wA);
                ffma2(acc[i][1], hh[i], wB);
            }
        }
        __syncthreads();
    }

    float bs[4];
    #pragma unroll
    for (int j = 0; j < 4; j++) {
        int jj = j0 + tx * 4 + j;
        bs[j] = bih[jj] + bhh[jj];
    }
    #pragma unroll
    for (int i = 0; i < 4; i++) {
        int b = b0 + ty * 4 + i;
        float a0, a1, a2, a3;
        unpack2(acc[i][0], a0, a1);
        unpack2(acc[i][1], a2, a3);
        float4 o;
        o.x = a0 + bs[0]; o.y = a1 + bs[1];
        o.z = a2 + bs[2]; o.w = a3 + bs[3];
        *(float4*)&g_xg[((size_t)t * Bx + b) * G4 + j0 + tx * 4] = o;
    }
}

// ---------------------------------------------------------------------------
// Scan step v3: tile [32 b x 16 j x 4 gates], 128 threads, grid (32, 16) = 512 blocks.
// Thread (tx=j, ty): 4 b x 1 j x 4 gates. Inner loop per k:
//   2 x LDS.128 (h pairs, broadcast) + 1 x LDS.128 (w: i,f,g,o) + 8 x FFMA2.
__global__ __launch_bounds__(128) void step_kernel(int t)
{
    __shared__ unsigned long long sh2[32][34];   // [k][b] = (h,h); row 272B (16B-mult)
    __shared__ float4 sw4[32][17];               // [k][j] = (wi,wf,wg,wo); row 272B
    const int tid = threadIdx.x;
    const int tx = tid & 15;          // j within tile
    const int ty = tid >> 4;          // 0..7 -> 4 b each
    const int jt = blockIdx.x;        // j tile (16 j)
    const int j0 = jt * 16, b0 = blockIdx.y * 32;

    const float* hprev = (t == 0) ? g_h0 : (g_hs + (size_t)(t - 1) * Bx * Hx);
    const float* xgt   = g_xg + (size_t)t * Bx * G4;
    float* hout        = g_hs + (size_t)t * Bx * Hx;
    const float* wtile = g_wr + (size_t)jt * (512 * 64);   // [k][j][g] contiguous

    // acc_if[i] = (gate_i, gate_f) for b-index i; acc_go[i] = (gate_g, gate_o)
    unsigned long long acc_if[4], acc_go[4];
    #pragma unroll
    for (int i = 0; i < 4; i++) { acc_if[i] = 0ULL; acc_go[i] = 0ULL; }

    // staging index for h: thread -> b row, k quarter
    const int sb = tid >> 2;          // 0..31 (b)
    const int sq = (tid & 3) * 8;     // 0,8,16,24 (k offset)

    for (int k0 = 0; k0 < Hx; k0 += 32) {
        // --- stage h (pre-duplicated pairs) ---
        {
            const float* hp = hprev + (size_t)(b0 + sb) * Hx + k0 + sq;
            float4 v0 = *(const float4*)(hp);
            float4 v1 = *(const float4*)(hp + 4);
            sh2[sq + 0][sb] = pack2(v0.x, v0.x);
            sh2[sq + 1][sb] = pack2(v0.y, v0.y);
            sh2[sq + 2][sb] = pack2(v0.z, v0.z);
            sh2[sq + 3][sb] = pack2(v0.w, v0.w);
            sh2[sq + 4][sb] = pack2(v1.x, v1.x);
            sh2[sq + 5][sb] = pack2(v1.y, v1.y);
            sh2[sq + 6][sb] = pack2(v1.z, v1.z);
            sh2[sq + 7][sb] = pack2(v1.w, v1.w);
        }
        // --- stage w: contiguous 8KB copy (32 k x 16 j x 16B) ---
        {
            const float4* src = (const float4*)(wtile + (size_t)k0 * 64);
            #pragma unroll
            for (int it = 0; it < 4; it++) {
                int s = tid + it * 128;          // float4 index 0..511
                int k = s >> 4, j = s & 15;
                sw4[k][j] = src[s];
            }
        }
        __syncthreads();
        #pragma unroll
        for (int k = 0; k < 32; k++) {
            // h pairs for 4 b (broadcast within warp halves)
            unsigned long long h01[2], h23[2];
            *(ulonglong2*)h01 = *(const ulonglong2*)&sh2[k][ty * 4];
            *(ulonglong2*)h23 = *(const ulonglong2*)&sh2[k][ty * 4 + 2];
            // w for this j: (wi,wf) and (wg,wo)
            ulonglong2 wv = *(const ulonglong2*)&sw4[k][tx];
            ffma2(acc_if[0], h01[0], wv.x); ffma2(acc_go[0], h01[0], wv.y);
            ffma2(acc_if[1], h01[1], wv.x); ffma2(acc_go[1], h01[1], wv.y);
            ffma2(acc_if[2], h23[0], wv.x); ffma2(acc_go[2], h23[0], wv.y);
            ffma2(acc_if[3], h23[1], wv.x); ffma2(acc_go[3], h23[1], wv.y);
        }
        __syncthreads();
    }

    // LSTM cell epilogue
    const int j = j0 + tx;
    #pragma unroll
    for (int i = 0; i < 4; i++) {
        int b = b0 + ty * 4 + i;
        const float* xb = xgt + (size_t)b * G4;
        float gi, gf, gg, go;
        unpack2(acc_if[i], gi, gf);
        unpack2(acc_go[i], gg, go);
        float vi = gi + xb[j];
        float vf = gf + xb[Hx + j];
        float vg = gg + xb[2 * Hx + j];
        float vo = go + xb[3 * Hx + j];
        float si = 1.f / (1.f + expf(-vi));
        float sf = 1.f / (1.f + expf(-vf));
        float tg = tanhf(vg);
        float so = 1.f / (1.f + expf(-vo));
        float cold = g_c[b * Hx + j];
        float cn = sf * cold + si * tg;
        g_c[b * Hx + j] = cn;
        hout[b * Hx + j] = so * tanhf(cn);
    }
}

// ---------------------------------------------------------------------------
// Per-t fused epilogue: fc1 -> BN1 -> leaky(0.1) -> fc2 -> BN2 -> relu
__device__ __forceinline__ void block_reduce2(float& a, float& b, float* ba, float* bb) {
    const unsigned m = 0xffffffffu;
    #pragma unroll
    for (int o = 16; o; o >>= 1) { a += __shfl_xor_sync(m, a, o); b += __shfl_xor_sync(m, b, o); }
    int lane = threadIdx.x & 31, wid = threadIdx.x >> 5;
    if (lane == 0) { ba[wid] = a; bb[wid] = b; }
    __syncthreads();
    if (wid == 0) {
        a = (lane < 16) ? ba[lane] : 0.f;
        b = (lane < 16) ? bb[lane] : 0.f;
        #pragma unroll
        for (int o = 8; o; o >>= 1) { a += __shfl_xor_sync(m, a, o); b += __shfl_xor_sync(m, b, o); }
        if (lane == 0) { ba[0] = a; bb[0] = b; }
    }
    __syncthreads();
    a = ba[0]; b = bb[0];
}

__global__ __launch_bounds__(512) void final_kernel(
    const float* __restrict__ fc1_w, const float* __restrict__ fc1_b,
    const float* __restrict__ fc2_w, const float* __restrict__ fc2_b,
    const float* __restrict__ bn1_g, const float* __restrict__ bn1_b,
    const float* __restrict__ bn2_g, const float* __restrict__ bn2_b,
    float* __restrict__ out)
{
    __shared__ float sW[128][32];
    __shared__ float ra[16], rb[16];
    const int t = blockIdx.x, b = threadIdx.x;

    float a[32];
    #pragma unroll
    for (int o = 0; o < 32; o++) a[o] = 0.f;

    for (int h0 = 0; h0 < Hx; h0 += 128) {
        __syncthreads();
        for (int idx = b; idx < 128 * 32; idx += 512) {
            int h = idx >> 5, o = idx & 31;
            sW[h][o] = fc1_w[(size_t)o * Hx + h0 + h];
        }
        __syncthreads();
        const float* hrow = g_hs + (size_t)t * Bx * Hx + (size_t)b * Hx + h0;
        for (int h = 0; h < 128; h += 4) {
            float4 hv = *(const float4*)(hrow + h);
            float hva[4] = {hv.x, hv.y, hv.z, hv.w};
            #pragma unroll
            for (int m = 0; m < 4; m++)
                #pragma unroll
                for (int o = 0; o < 32; o++) a[o] += hva[m] * sW[h + m][o];
        }
    }

    float s = 0.f, ss = 0.f;
    #pragma unroll
    for (int o = 0; o < 32; o++) {
        a[o] += fc1_b[o];
        s += a[o]; ss += a[o] * a[o];
    }
    block_reduce2(s, ss, ra, rb);
    const float invN1 = 1.f / (512.f * 32.f);
    float m1 = s * invN1;
    float v1 = ss * invN1 - m1 * m1;
    float sc1 = rsqrtf(v1 + 1e-5f) * bn1_g[t];
    float sh1 = bn1_b[t];

    float z = fc2_b[0];
    #pragma unroll
    for (int o = 0; o < 32; o++) {
        float an = (a[o] - m1) * sc1 + sh1;
        an = (an < 0.f) ? 0.1f * an : an;
        z += an * fc2_w[o];
    }

    float zs = z, zss = z * z;
    block_reduce2(zs, zss, ra, rb);
    float m2 = zs * (1.f / 512.f);
    float v2 = zss * (1.f / 512.f) - m2 * m2;
    float zn = (z - m2) * rsqrtf(v2 + 1e-5f) * bn2_g[t] + bn2_b[t];
    out[(size_t)b * Tx + t] = fmaxf(zn, 0.f);
}

// ---------------------------------------------------------------------------
extern "C" void kernel_launch(void* const* d_in, const int* in_sizes, int n_in,
                              void* d_out, int out_size)
{
    const float* x     = (const float*)d_in[0];
    const float* Wih   = (const float*)d_in[1];
    const float* Whh   = (const float*)d_in[2];
    const float* bih   = (const float*)d_in[3];
    const float* bhh   = (const float*)d_in[4];
    const float* fc1_w = (const float*)d_in[5];
    const float* fc1_b = (const float*)d_in[6];
    const float* fc2_w = (const float*)d_in[7];
    const float* fc2_b = (const float*)d_in[8];
    const float* bn1_g = (const float*)d_in[9];
    const float* bn1_b = (const float*)d_in[10];
    const float* bn2_g = (const float*)d_in[11];
    const float* bn2_b = (const float*)d_in[12];
    float* out = (float*)d_out;

    init_kernel<<<(Bx * Hx + 255) / 256, 256>>>();
    reorg_kernel<<<(Hx * G4 + 255) / 256, 256>>>(Whh);

    pregemm_kernel<<<dim3(G4 / 64, Bx / 64, Tx), 256>>>(x, Wih, bih, bhh);

    for (int t = 0; t < Tx; t++)
        step_kernel<<<dim3(Hx / 16, Bx / 32), 128>>>(t);

    final_kernel<<<Tx, 512>>>(fc1_w, fc1_b, fc2_w, fc2_b,
                              bn1_g, bn1_b, bn2_g, bn2_b, out);
}